// round 11
// baseline (speedup 1.0000x reference)
#include <cuda_runtime.h>

// AUGRU: B=65536, T=50, E=10.
// r6 (170us, best): scalar LDCU weights, issue-bound 71% @ ~1330 instr/warp-step
//   (600 FFMA + 600 scalar LDCU + glue). r10 (2 rows/thread) proved 1.73
//   warps/SMSP cannot hide latency -> keep 1 row/thread, 3.46 warps/SMSP.
// THIS ROUND (single change vs r6): weight rows padded to 12 floats (16B-
// aligned) and read as float4+float4+float2. Consumer is scalar FFMA (accepts
// UR operand), addresses are literal+uniform -> ptxas can emit LDCU.128/.64
// into uniform regs: 600 weight loads -> 180. Predict ~990 instr/warp-step.
// (Pre-registered failure: GPR-dest LDC.128 half-rate port -> r7 signature.)

#define E_   10
#define EP   12            // padded row stride (48B, 16B-aligned rows)
#define T_   50
#define BTOT 65536
#define ROWS_PER_CTA 128
#define NTHR 128
#define TC   2

// Layout: weights [m*120 + j*12 + k] = W'_m[k][j] (transposed, k=10,11 zero),
//         m: 0=Wi_r,1=Wh_r,2=Wi_z,3=Wh_z,4=Wi_h,5=Wh_h  (W' = W@Ws fused)
//         biases  [720 + m*10 + j], m: 0=r,1=z,2=h
#define PSZ (6 * 120 + 3 * E_)
__device__   __align__(16) float gAll[PSZ];
__constant__ __align__(16) float cAll[PSZ];

__global__ void prep_kernel(
    const float* __restrict__ WiR, const float* __restrict__ biR, const float* __restrict__ WhR,
    const float* __restrict__ WsR, const float* __restrict__ bsR,
    const float* __restrict__ WiZ, const float* __restrict__ biZ, const float* __restrict__ WhZ,
    const float* __restrict__ WsZ, const float* __restrict__ bsZ,
    const float* __restrict__ WiH, const float* __restrict__ biH, const float* __restrict__ WhH,
    const float* __restrict__ WtH, const float* __restrict__ btH)
{
    const int t = threadIdx.x;
    const float* Am[6] = {WiR, WhR, WiZ, WhZ, WiH, WhH};
    const float* Bm[6] = {WsR, WsR, WsZ, WsZ, WtH, WtH};
    if (t < 120) {
        int j = t / EP;   // output col of fused W' (0..9)
        int k = t % EP;   // input row (0..11; 10,11 padding)
#pragma unroll
        for (int m = 0; m < 6; m++) {
            float s = 0.0f;
            if (k < E_) {
#pragma unroll
                for (int l = 0; l < E_; l++)
                    s = fmaf(Am[m][k * E_ + l], Bm[m][l * E_ + j], s);
            }
            gAll[m * 120 + j * EP + k] = s;   // transposed, padded store
        }
    }
    const float* bi[3] = {biR, biZ, biH};
    const float* bs[3] = {bsR, bsZ, btH};
    const float* Wo[3] = {WsR, WsZ, WtH};
    if (t < E_) {
#pragma unroll
        for (int m = 0; m < 3; m++) {
            float s = bs[m][t];
#pragma unroll
            for (int l = 0; l < E_; l++)
                s = fmaf(bi[m][l], Wo[m][l * E_ + t], s);
            gAll[720 + m * E_ + t] = s;
        }
    }
}

// sigmoid / tanh, safe at extremes (exp->inf => rcp->0). Proven rel_err 2e-7.
__device__ __forceinline__ float sigm(float v) {
    float e = __expf(-v);
    return __fdividef(1.0f, 1.0f + e);
}
__device__ __forceinline__ float tanh_f(float v) {
    float e = __expf(2.0f * v);
    return 1.0f - __fdividef(2.0f, 1.0f + e);
}

// acc[j] += dot(s, W'[:,j]); W' rows read as float4+float4+float2 from
// __constant__ at literal offsets (uniform addresses -> LDCU.128/.64 path).
// __syncwarp every 5 output rows bounds the load-batching window (anti-spill).
template <int OFF>
__device__ __forceinline__ void mvc(const float* s, float* acc) {
#pragma unroll
    for (int j = 0; j < E_; j++) {
        const float4 w0 = *reinterpret_cast<const float4*>(&cAll[OFF + j * EP]);
        const float4 w1 = *reinterpret_cast<const float4*>(&cAll[OFF + j * EP + 4]);
        const float2 w2 = *reinterpret_cast<const float2*>(&cAll[OFF + j * EP + 8]);
        float a = acc[j];
        a = fmaf(s[0], w0.x, a); a = fmaf(s[1], w0.y, a);
        a = fmaf(s[2], w0.z, a); a = fmaf(s[3], w0.w, a);
        a = fmaf(s[4], w1.x, a); a = fmaf(s[5], w1.y, a);
        a = fmaf(s[6], w1.z, a); a = fmaf(s[7], w1.w, a);
        a = fmaf(s[8], w2.x, a); a = fmaf(s[9], w2.y, a);
        acc[j] = a;
        if (j == 4) __syncwarp();
    }
    __syncwarp();
}

__global__ void __launch_bounds__(NTHR, 4) augru_kernel(
    const float* __restrict__ X, const float* __restrict__ A,
    const float* __restrict__ H0, float* __restrict__ Out)
{
    __shared__ __align__(16) float xsf[TC][E_][ROWS_PER_CTA];
    __shared__ __align__(16) float asf[TC][E_][ROWS_PER_CTA];

    const int tid = threadIdx.x;           // owns row rowBase+tid
    const int rowBase = blockIdx.x * ROWS_PER_CTA;

    // init h (broadcast h0)
    float h[E_];
#pragma unroll
    for (int e = 0; e < E_; e++)
        h[e] = H0[e];

    const float4* Xg = reinterpret_cast<const float4*>(X);
    const float4* Ag = reinterpret_cast<const float4*>(A);

#pragma unroll 1
    for (int t0 = 0; t0 < T_; t0 += TC) {
        __syncthreads();
        // ---- stage 2 steps of x,a for 128 rows (coalesced float4) ----
        // per row: 2*10 floats = 5 float4, contiguous. row stride = 125 float4.
        {
            const long cbase = (long)(t0 * E_) / 4;  // exact: t0 even
#pragma unroll
            for (int it = 0; it < 5; ++it) {
                int idx = it * NTHR + tid;           // 0..639
                int r = idx / 5, v = idx % 5;
                long g = (long)(rowBase + r) * 125 + cbase + v;
                float4 dx = Xg[g];
                float4 da = Ag[g];
#pragma unroll
                for (int c = 0; c < 4; c++) {
                    int q = v * 4 + c;
                    int tl = (q >= E_) ? 1 : 0;
                    int e = q - E_ * tl;
                    float fx = (c == 0) ? dx.x : (c == 1) ? dx.y : (c == 2) ? dx.z : dx.w;
                    float fa = (c == 0) ? da.x : (c == 1) ? da.y : (c == 2) ? da.z : da.w;
                    xsf[tl][e][r] = fx;
                    asf[tl][e][r] = fa;
                }
            }
        }
        __syncthreads();

#pragma unroll 1
        for (int tt = 0; tt < TC; ++tt) {
            float x[E_];
#pragma unroll
            for (int e = 0; e < E_; e++)
                x[e] = xsf[tt][e][tid];

            float acc[E_], r[E_], hz[E_];

            // ---------------- z gate (fused) ----------------
#pragma unroll
            for (int j = 0; j < E_; j++) acc[j] = cAll[720 + E_ + j];
            mvc<240>(x, acc);   // x @ Wi_z'
            mvc<360>(h, acc);   // h @ Wh_z'
#pragma unroll
            for (int j = 0; j < E_; j++) hz[j] = h[j] * sigm(acc[j]);

            // ---------------- r gate (fused) ----------------
#pragma unroll
            for (int j = 0; j < E_; j++) acc[j] = cAll[720 + j];
            mvc<0>(x, acc);     // x @ Wi_r'
            mvc<120>(h, acc);   // h @ Wh_r'
#pragma unroll
            for (int j = 0; j < E_; j++) r[j] = sigm(acc[j]);

            // ---------------- candidate (fused) ----------------
#pragma unroll
            for (int j = 0; j < E_; j++) acc[j] = cAll[720 + 2 * E_ + j];
            mvc<480>(x, acc);   // x dead after this
            mvc<600>(hz, acc);  // hz dead after this

            // ---------------- h update ----------------
#pragma unroll
            for (int e = 0; e < E_; e++) {
                float c  = tanh_f(acc[e]);
                float Ra = asf[tt][e][tid] * r[e];
                h[e] += Ra * (c - h[e]);
            }
        }
    }

    // ---- store final h ----
    const long r0 = (long)(rowBase + tid) * E_;
#pragma unroll
    for (int e = 0; e < E_; e++)
        Out[r0 + e] = h[e];
}

extern "C" void kernel_launch(void* const* d_in, const int* in_sizes, int n_in,
                              void* d_out, int out_size) {
    const float* X   = (const float*)d_in[0];
    const float* A   = (const float*)d_in[1];
    const float* H0  = (const float*)d_in[2];
    const float* WiR = (const float*)d_in[3];
    const float* biR = (const float*)d_in[4];
    const float* WhR = (const float*)d_in[5];
    const float* WsR = (const float*)d_in[6];
    const float* bsR = (const float*)d_in[7];
    const float* WiZ = (const float*)d_in[8];
    const float* biZ = (const float*)d_in[9];
    const float* WhZ = (const float*)d_in[10];
    const float* WsZ = (const float*)d_in[11];
    const float* bsZ = (const float*)d_in[12];
    const float* WiH = (const float*)d_in[13];
    const float* biH = (const float*)d_in[14];
    const float* WhH = (const float*)d_in[15];
    const float* WtH = (const float*)d_in[16];
    const float* btH = (const float*)d_in[17];
    float* Out = (float*)d_out;

    prep_kernel<<<1, 128>>>(WiR, biR, WhR, WsR, bsR,
                            WiZ, biZ, WhZ, WsZ, bsZ,
                            WiH, biH, WhH, WtH, btH);

    // fused params -> constant bank (D2D memcpy, graph-capturable)
    void* gsym = nullptr;
    cudaGetSymbolAddress(&gsym, gAll);
    cudaMemcpyToSymbolAsync(cAll, gsym, PSZ * sizeof(float), 0,
                            cudaMemcpyDeviceToDevice, 0);

    dim3 grid(BTOT / ROWS_PER_CTA);  // 512
    dim3 block(NTHR);                // 128
    augru_kernel<<<grid, block>>>(X, A, H0, Out);
}

// round 12
// speedup vs baseline: 1.6227x; 1.6227x over previous
#include <cuda_runtime.h>

// AUGRU: B=65536, T=50, E=10.
// r6 (170us) = validated inner loop: scalar __constant__ weights (ptxas auto-
// merges adjacent literal reads on the uniform path -- r11 proved manual
// float4 const reads REGRESS to ~2000 instr/warp-step). This round keeps the
// r6 inner loop byte-identical and removes two non-instruction losses:
//  1) CTA balance: 1024 CTAs x 64 thr (was 512x128). 512/148 left 68 SMs with
//     4 CTAs vs 80 with 3 (15% imbalance); 1024/148 -> 7 vs 6 (1.4%).
//  2) WARPSYNC: 12 -> 6 fences/step (end-of-matvec only), ~23cyc each.

#define E_   10
#define T_   50
#define BTOT 65536
#define ROWS_PER_CTA 64
#define NTHR 64
#define TC   2

// Flat fused parameter block (scalar):
//  [m*100 + j*10 + k] = W'_m[k][j]  (transposed), m: 0=Wi_r,1=Wh_r,2=Wi_z,3=Wh_z,4=Wi_h,5=Wh_h
//  [600 + m*10 + j]   = fused bias, m: 0=r,1=z,2=h
#define PSZ (6 * 100 + 3 * E_)
__device__   float gAll[PSZ];
__constant__ float cAll[PSZ];

__global__ void prep_kernel(
    const float* __restrict__ WiR, const float* __restrict__ biR, const float* __restrict__ WhR,
    const float* __restrict__ WsR, const float* __restrict__ bsR,
    const float* __restrict__ WiZ, const float* __restrict__ biZ, const float* __restrict__ WhZ,
    const float* __restrict__ WsZ, const float* __restrict__ bsZ,
    const float* __restrict__ WiH, const float* __restrict__ biH, const float* __restrict__ WhH,
    const float* __restrict__ WtH, const float* __restrict__ btH)
{
    const int t = threadIdx.x;
    const float* Am[6] = {WiR, WhR, WiZ, WhZ, WiH, WhH};
    const float* Bm[6] = {WsR, WsR, WsZ, WsZ, WtH, WtH};
    if (t < 100) {
        int j = t / E_;   // output col of fused W'
        int k = t % E_;   // input row
#pragma unroll
        for (int m = 0; m < 6; m++) {
            float s = 0.0f;
#pragma unroll
            for (int l = 0; l < E_; l++)
                s = fmaf(Am[m][k * E_ + l], Bm[m][l * E_ + j], s);
            gAll[m * 100 + j * E_ + k] = s;   // transposed store
        }
    }
    const float* bi[3] = {biR, biZ, biH};
    const float* bs[3] = {bsR, bsZ, btH};
    const float* Wo[3] = {WsR, WsZ, WtH};
    if (t < E_) {
#pragma unroll
        for (int m = 0; m < 3; m++) {
            float s = bs[m][t];
#pragma unroll
            for (int l = 0; l < E_; l++)
                s = fmaf(bi[m][l], Wo[m][l * E_ + t], s);
            gAll[600 + m * E_ + t] = s;
        }
    }
}

// sigmoid / tanh, safe at extremes (exp->inf => rcp->0). Proven rel_err 2e-7.
__device__ __forceinline__ float sigm(float v) {
    float e = __expf(-v);
    return __fdividef(1.0f, 1.0f + e);
}
__device__ __forceinline__ float tanh_f(float v) {
    float e = __expf(2.0f * v);
    return 1.0f - __fdividef(2.0f, 1.0f + e);
}

// acc[j] += dot(s, W'[:,j]) with W' in __constant__ at literal offsets
// (scalar reads -> ptxas merges onto the uniform/LDCU path; do NOT hand-
// vectorize, r11 regression). One __syncwarp per matvec bounds the load-
// batching window (anti-spill).
template <int OFF>
__device__ __forceinline__ void mvc(const float* s, float* acc) {
#pragma unroll
    for (int j = 0; j < E_; j++) {
        float a = acc[j];
#pragma unroll
        for (int k = 0; k < E_; k++)
            a = fmaf(s[k], cAll[OFF + j * E_ + k], a);
        acc[j] = a;
    }
    __syncwarp();
}

__global__ void __launch_bounds__(NTHR, 8) augru_kernel(
    const float* __restrict__ X, const float* __restrict__ A,
    const float* __restrict__ H0, float* __restrict__ Out)
{
    __shared__ __align__(16) float xsf[TC][E_][ROWS_PER_CTA];
    __shared__ __align__(16) float asf[TC][E_][ROWS_PER_CTA];

    const int tid = threadIdx.x;           // owns row rowBase+tid
    const int rowBase = blockIdx.x * ROWS_PER_CTA;

    // init h (broadcast h0)
    float h[E_];
#pragma unroll
    for (int e = 0; e < E_; e++)
        h[e] = H0[e];

    const float4* Xg = reinterpret_cast<const float4*>(X);
    const float4* Ag = reinterpret_cast<const float4*>(A);

#pragma unroll 1
    for (int t0 = 0; t0 < T_; t0 += TC) {
        __syncthreads();
        // ---- stage 2 steps of x,a for 64 rows (coalesced float4) ----
        // per row: 2*10 floats = 5 float4, contiguous. row stride = 125 float4.
        {
            const long cbase = (long)(t0 * E_) / 4;  // exact: t0 even
#pragma unroll
            for (int it = 0; it < 5; ++it) {
                int idx = it * NTHR + tid;           // 0..319
                int r = idx / 5, v = idx % 5;
                long g = (long)(rowBase + r) * 125 + cbase + v;
                float4 dx = Xg[g];
                float4 da = Ag[g];
#pragma unroll
                for (int c = 0; c < 4; c++) {
                    int q = v * 4 + c;
                    int tl = (q >= E_) ? 1 : 0;
                    int e = q - E_ * tl;
                    float fx = (c == 0) ? dx.x : (c == 1) ? dx.y : (c == 2) ? dx.z : dx.w;
                    float fa = (c == 0) ? da.x : (c == 1) ? da.y : (c == 2) ? da.z : da.w;
                    xsf[tl][e][r] = fx;
                    asf[tl][e][r] = fa;
                }
            }
        }
        __syncthreads();

#pragma unroll 1
        for (int tt = 0; tt < TC; ++tt) {
            float x[E_];
#pragma unroll
            for (int e = 0; e < E_; e++)
                x[e] = xsf[tt][e][tid];

            float acc[E_], r[E_], hz[E_];

            // ---------------- z gate (fused) ----------------
#pragma unroll
            for (int j = 0; j < E_; j++) acc[j] = cAll[600 + E_ + j];
            mvc<200>(x, acc);   // x @ Wi_z'
            mvc<300>(h, acc);   // h @ Wh_z'
#pragma unroll
            for (int j = 0; j < E_; j++) hz[j] = h[j] * sigm(acc[j]);

            // ---------------- r gate (fused) ----------------
#pragma unroll
            for (int j = 0; j < E_; j++) acc[j] = cAll[600 + j];
            mvc<0>(x, acc);     // x @ Wi_r'
            mvc<100>(h, acc);   // h @ Wh_r'
#pragma unroll
            for (int j = 0; j < E_; j++) r[j] = sigm(acc[j]);

            // ---------------- candidate (fused) ----------------
#pragma unroll
            for (int j = 0; j < E_; j++) acc[j] = cAll[600 + 2 * E_ + j];
            mvc<400>(x, acc);   // x dead after this
            mvc<500>(hz, acc);  // hz dead after this

            // ---------------- h update ----------------
#pragma unroll
            for (int e = 0; e < E_; e++) {
                float c  = tanh_f(acc[e]);
                float Ra = asf[tt][e][tid] * r[e];
                h[e] += Ra * (c - h[e]);
            }
        }
    }

    // ---- store final h ----
    const long r0 = (long)(rowBase + tid) * E_;
#pragma unroll
    for (int e = 0; e < E_; e++)
        Out[r0 + e] = h[e];
}

extern "C" void kernel_launch(void* const* d_in, const int* in_sizes, int n_in,
                              void* d_out, int out_size) {
    const float* X   = (const float*)d_in[0];
    const float* A   = (const float*)d_in[1];
    const float* H0  = (const float*)d_in[2];
    const float* WiR = (const float*)d_in[3];
    const float* biR = (const float*)d_in[4];
    const float* WhR = (const float*)d_in[5];
    const float* WsR = (const float*)d_in[6];
    const float* bsR = (const float*)d_in[7];
    const float* WiZ = (const float*)d_in[8];
    const float* biZ = (const float*)d_in[9];
    const float* WhZ = (const float*)d_in[10];
    const float* WsZ = (const float*)d_in[11];
    const float* bsZ = (const float*)d_in[12];
    const float* WiH = (const float*)d_in[13];
    const float* biH = (const float*)d_in[14];
    const float* WhH = (const float*)d_in[15];
    const float* WtH = (const float*)d_in[16];
    const float* btH = (const float*)d_in[17];
    float* Out = (float*)d_out;

    prep_kernel<<<1, 128>>>(WiR, biR, WhR, WsR, bsR,
                            WiZ, biZ, WhZ, WsZ, bsZ,
                            WiH, biH, WhH, WtH, btH);

    // fused params -> constant bank (D2D memcpy, graph-capturable)
    void* gsym = nullptr;
    cudaGetSymbolAddress(&gsym, gAll);
    cudaMemcpyToSymbolAsync(cAll, gsym, PSZ * sizeof(float), 0,
                            cudaMemcpyDeviceToDevice, 0);

    dim3 grid(BTOT / ROWS_PER_CTA);  // 1024
    dim3 block(NTHR);                // 64
    augru_kernel<<<grid, block>>>(X, A, H0, Out);
}

// round 13
// speedup vs baseline: 1.7043x; 1.0503x over previous
#include <cuda_runtime.h>

// AUGRU: B=65536, T=50, E=10.
// r6 (170us) = validated inner loop: scalar __constant__ weights (ptxas auto-
// merges adjacent literal reads on the uniform path -- r11 proved manual
// float4 const reads REGRESS to ~2000 instr/warp-step). This round keeps the
// r6 inner loop byte-identical and removes two non-instruction losses:
//  1) CTA balance: 1024 CTAs x 64 thr (was 512x128). 512/148 left 68 SMs with
//     4 CTAs vs 80 with 3 (15% imbalance); 1024/148 -> 7 vs 6 (1.4%).
//  2) WARPSYNC: 12 -> 6 fences/step (end-of-matvec only), ~23cyc each.

#define E_   10
#define T_   50
#define BTOT 65536
#define ROWS_PER_CTA 64
#define NTHR 64
#define TC   2

// Flat fused parameter block (scalar):
//  [m*100 + j*10 + k] = W'_m[k][j]  (transposed), m: 0=Wi_r,1=Wh_r,2=Wi_z,3=Wh_z,4=Wi_h,5=Wh_h
//  [600 + m*10 + j]   = fused bias, m: 0=r,1=z,2=h
#define PSZ (6 * 100 + 3 * E_)
__device__   float gAll[PSZ];
__constant__ float cAll[PSZ];

__global__ void prep_kernel(
    const float* __restrict__ WiR, const float* __restrict__ biR, const float* __restrict__ WhR,
    const float* __restrict__ WsR, const float* __restrict__ bsR,
    const float* __restrict__ WiZ, const float* __restrict__ biZ, const float* __restrict__ WhZ,
    const float* __restrict__ WsZ, const float* __restrict__ bsZ,
    const float* __restrict__ WiH, const float* __restrict__ biH, const float* __restrict__ WhH,
    const float* __restrict__ WtH, const float* __restrict__ btH)
{
    const int t = threadIdx.x;
    const float* Am[6] = {WiR, WhR, WiZ, WhZ, WiH, WhH};
    const float* Bm[6] = {WsR, WsR, WsZ, WsZ, WtH, WtH};
    if (t < 100) {
        int j = t / E_;   // output col of fused W'
        int k = t % E_;   // input row
#pragma unroll
        for (int m = 0; m < 6; m++) {
            float s = 0.0f;
#pragma unroll
            for (int l = 0; l < E_; l++)
                s = fmaf(Am[m][k * E_ + l], Bm[m][l * E_ + j], s);
            gAll[m * 100 + j * E_ + k] = s;   // transposed store
        }
    }
    const float* bi[3] = {biR, biZ, biH};
    const float* bs[3] = {bsR, bsZ, btH};
    const float* Wo[3] = {WsR, WsZ, WtH};
    if (t < E_) {
#pragma unroll
        for (int m = 0; m < 3; m++) {
            float s = bs[m][t];
#pragma unroll
            for (int l = 0; l < E_; l++)
                s = fmaf(bi[m][l], Wo[m][l * E_ + t], s);
            gAll[600 + m * E_ + t] = s;
        }
    }
}

// sigmoid / tanh, safe at extremes (exp->inf => rcp->0). Proven rel_err 2e-7.
__device__ __forceinline__ float sigm(float v) {
    float e = __expf(-v);
    return __fdividef(1.0f, 1.0f + e);
}
__device__ __forceinline__ float tanh_f(float v) {
    float e = __expf(2.0f * v);
    return 1.0f - __fdividef(2.0f, 1.0f + e);
}

// acc[j] += dot(s, W'[:,j]) with W' in __constant__ at literal offsets
// (scalar reads -> ptxas merges onto the uniform/LDCU path; do NOT hand-
// vectorize, r11 regression). One __syncwarp per matvec bounds the load-
// batching window (anti-spill).
template <int OFF>
__device__ __forceinline__ void mvc(const float* s, float* acc) {
#pragma unroll
    for (int j = 0; j < E_; j++) {
        float a = acc[j];
#pragma unroll
        for (int k = 0; k < E_; k++)
            a = fmaf(s[k], cAll[OFF + j * E_ + k], a);
        acc[j] = a;
    }
    __syncwarp();
}

__global__ void __launch_bounds__(NTHR, 8) augru_kernel(
    const float* __restrict__ X, const float* __restrict__ A,
    const float* __restrict__ H0, float* __restrict__ Out)
{
    __shared__ __align__(16) float xsf[TC][E_][ROWS_PER_CTA];
    __shared__ __align__(16) float asf[TC][E_][ROWS_PER_CTA];

    const int tid = threadIdx.x;           // owns row rowBase+tid
    const int rowBase = blockIdx.x * ROWS_PER_CTA;

    // init h (broadcast h0)
    float h[E_];
#pragma unroll
    for (int e = 0; e < E_; e++)
        h[e] = H0[e];

    const float4* Xg = reinterpret_cast<const float4*>(X);
    const float4* Ag = reinterpret_cast<const float4*>(A);

#pragma unroll 1
    for (int t0 = 0; t0 < T_; t0 += TC) {
        __syncthreads();
        // ---- stage 2 steps of x,a for 64 rows (coalesced float4) ----
        // per row: 2*10 floats = 5 float4, contiguous. row stride = 125 float4.
        {
            const long cbase = (long)(t0 * E_) / 4;  // exact: t0 even
#pragma unroll
            for (int it = 0; it < 5; ++it) {
                int idx = it * NTHR + tid;           // 0..319
                int r = idx / 5, v = idx % 5;
                long g = (long)(rowBase + r) * 125 + cbase + v;
                float4 dx = Xg[g];
                float4 da = Ag[g];
#pragma unroll
                for (int c = 0; c < 4; c++) {
                    int q = v * 4 + c;
                    int tl = (q >= E_) ? 1 : 0;
                    int e = q - E_ * tl;
                    float fx = (c == 0) ? dx.x : (c == 1) ? dx.y : (c == 2) ? dx.z : dx.w;
                    float fa = (c == 0) ? da.x : (c == 1) ? da.y : (c == 2) ? da.z : da.w;
                    xsf[tl][e][r] = fx;
                    asf[tl][e][r] = fa;
                }
            }
        }
        __syncthreads();

#pragma unroll 1
        for (int tt = 0; tt < TC; ++tt) {
            float x[E_];
#pragma unroll
            for (int e = 0; e < E_; e++)
                x[e] = xsf[tt][e][tid];

            float acc[E_], r[E_], hz[E_];

            // ---------------- z gate (fused) ----------------
#pragma unroll
            for (int j = 0; j < E_; j++) acc[j] = cAll[600 + E_ + j];
            mvc<200>(x, acc);   // x @ Wi_z'
            mvc<300>(h, acc);   // h @ Wh_z'
#pragma unroll
            for (int j = 0; j < E_; j++) hz[j] = h[j] * sigm(acc[j]);

            // ---------------- r gate (fused) ----------------
#pragma unroll
            for (int j = 0; j < E_; j++) acc[j] = cAll[600 + j];
            mvc<0>(x, acc);     // x @ Wi_r'
            mvc<100>(h, acc);   // h @ Wh_r'
#pragma unroll
            for (int j = 0; j < E_; j++) r[j] = sigm(acc[j]);

            // ---------------- candidate (fused) ----------------
#pragma unroll
            for (int j = 0; j < E_; j++) acc[j] = cAll[600 + 2 * E_ + j];
            mvc<400>(x, acc);   // x dead after this
            mvc<500>(hz, acc);  // hz dead after this

            // ---------------- h update ----------------
#pragma unroll
            for (int e = 0; e < E_; e++) {
                float c  = tanh_f(acc[e]);
                float Ra = asf[tt][e][tid] * r[e];
                h[e] += Ra * (c - h[e]);
            }
        }
    }

    // ---- store final h ----
    const long r0 = (long)(rowBase + tid) * E_;
#pragma unroll
    for (int e = 0; e < E_; e++)
        Out[r0 + e] = h[e];
}

extern "C" void kernel_launch(void* const* d_in, const int* in_sizes, int n_in,
                              void* d_out, int out_size) {
    const float* X   = (const float*)d_in[0];
    const float* A   = (const float*)d_in[1];
    const float* H0  = (const float*)d_in[2];
    const float* WiR = (const float*)d_in[3];
    const float* biR = (const float*)d_in[4];
    const float* WhR = (const float*)d_in[5];
    const float* WsR = (const float*)d_in[6];
    const float* bsR = (const float*)d_in[7];
    const float* WiZ = (const float*)d_in[8];
    const float* biZ = (const float*)d_in[9];
    const float* WhZ = (const float*)d_in[10];
    const float* WsZ = (const float*)d_in[11];
    const float* bsZ = (const float*)d_in[12];
    const float* WiH = (const float*)d_in[13];
    const float* biH = (const float*)d_in[14];
    const float* WhH = (const float*)d_in[15];
    const float* WtH = (const float*)d_in[16];
    const float* btH = (const float*)d_in[17];
    float* Out = (float*)d_out;

    prep_kernel<<<1, 128>>>(WiR, biR, WhR, WsR, bsR,
                            WiZ, biZ, WhZ, WsZ, bsZ,
                            WiH, biH, WhH, WtH, btH);

    // fused params -> constant bank (D2D memcpy, graph-capturable)
    void* gsym = nullptr;
    cudaGetSymbolAddress(&gsym, gAll);
    cudaMemcpyToSymbolAsync(cAll, gsym, PSZ * sizeof(float), 0,
                            cudaMemcpyDeviceToDevice, 0);

    dim3 grid(BTOT / ROWS_PER_CTA);  // 1024
    dim3 block(NTHR);                // 64
    augru_kernel<<<grid, block>>>(X, A, H0, Out);
}

// round 14
// speedup vs baseline: 2.0277x; 1.1898x over previous
#include <cuda_runtime.h>
#include <cuda_bf16.h>

// AUGRU: B=65536, T=50, E=10 — tensor-core path (mma.sync.m16n8k16 bf16,
// two-term hi/lo split). Weights = register-resident B-fragments; D->A
// chaining is in-lane (m16n8k16 D cols {2t,2t+1} == A k-cols per lane).
// Bias folded as weight row 10, x col 10 := 1.0. Cols/rows 10..15 padded 0.

#define E_   10
#define T_   50
#define BTOT 65536
#define ROWS_PER_CTA 64
#define NTHR 128
#define TC   2
#define XP   18           // staging row pitch (floats)

typedef unsigned int u32;

// B-fragments: [(((m*2+nt)*2+term)*2+reg)*32 + lane]
// m: 0=Wx_r,1=Wh_r,2=Wx_z,3=Wh_z,4=Wx_c,5=Wh_c (x-side holds bias row 10)
__device__ u32 gB[1536];

// pack: low16 = bf16(lo), high16 = bf16(hi)  (PTX: first src -> high half)
__device__ __forceinline__ u32 packbf(float lo, float hi) {
    u32 r; asm("cvt.rn.bf16x2.f32 %0, %1, %2;" : "=r"(r) : "f"(hi), "f"(lo));
    return r;
}
// split (v0,v1) into hi bf16x2 and residual-lo bf16x2
__device__ __forceinline__ void split2(float v0, float v1, u32& hi_, u32& lo_) {
    u32 h = packbf(v0, v1);
    float h0 = __uint_as_float(h << 16);
    float h1 = __uint_as_float(h & 0xffff0000u);
    hi_ = h;
    lo_ = packbf(v0 - h0, v1 - h1);
}

__global__ void prep_kernel(
    const float* __restrict__ WiR, const float* __restrict__ biR, const float* __restrict__ WhR,
    const float* __restrict__ WsR, const float* __restrict__ bsR,
    const float* __restrict__ WiZ, const float* __restrict__ biZ, const float* __restrict__ WhZ,
    const float* __restrict__ WsZ, const float* __restrict__ bsZ,
    const float* __restrict__ WiH, const float* __restrict__ biH, const float* __restrict__ WhH,
    const float* __restrict__ WtH, const float* __restrict__ btH)
{
    __shared__ float Wf[6][16][16];   // [m][k][n], zero-padded
    const int t = threadIdx.x;        // 256 threads
    for (int i = t; i < 6 * 256; i += 256)
        (&Wf[0][0][0])[i] = 0.0f;
    __syncthreads();

    const float* Am[6] = {WiR, WhR, WiZ, WhZ, WiH, WhH};
    const float* Bm[6] = {WsR, WsR, WsZ, WsZ, WtH, WtH};
    if (t < 100) {
        int k = t / E_, j = t % E_;
#pragma unroll
        for (int m = 0; m < 6; m++) {
            float s = 0.0f;
#pragma unroll
            for (int l = 0; l < E_; l++)
                s = fmaf(Am[m][k * E_ + l], Bm[m][l * E_ + j], s);
            Wf[m][k][j] = s;
        }
    }
    const float* bi[3] = {biR, biZ, biH};
    const float* bs[3] = {bsR, bsZ, btH};
    const float* Wo[3] = {WsR, WsZ, WtH};
    if (t < E_) {
#pragma unroll
        for (int m = 0; m < 3; m++) {
            float s = bs[m][t];
#pragma unroll
            for (int l = 0; l < E_; l++)
                s = fmaf(bi[m][l], Wo[m][l * E_ + t], s);
            Wf[2 * m][10][t] = s;     // bias -> x-side row 10 (m=0,2,4)
        }
    }
    __syncthreads();

    // pack B fragments (m16n8k16 col-major B: b0 k-rows {2t,2t+1}, b1 +8; col=g)
    for (int i = t; i < 1536; i += 256) {
        int lane = i & 31; int j = i >> 5;
        int reg = j & 1; j >>= 1;
        int term = j & 1; j >>= 1;
        int nt = j & 1; int m = j >> 1;
        int g = lane >> 2, tig = lane & 3;
        int k0 = 2 * tig + (reg ? 8 : 0);
        int col = nt * 8 + g;
        u32 hi, lo;
        split2(Wf[m][k0][col], Wf[m][k0 + 1][col], hi, lo);
        gB[i] = term ? lo : hi;
    }
}

__device__ __forceinline__ float sigm(float v) {
    float e = __expf(-v);
    return __fdividef(1.0f, 1.0f + e);
}
__device__ __forceinline__ float tanh_f(float v) {
    float e = __expf(2.0f * v);
    return 1.0f - __fdividef(2.0f, 1.0f + e);
}

__device__ __forceinline__ void mma16816(float* d, const u32* a, const u32* b) {
    asm("mma.sync.aligned.m16n8k16.row.col.f32.bf16.bf16.f32 "
        "{%0,%1,%2,%3},{%4,%5,%6,%7},{%8,%9},{%0,%1,%2,%3};"
        : "+f"(d[0]), "+f"(d[1]), "+f"(d[2]), "+f"(d[3])
        : "r"(a[0]), "r"(a[1]), "r"(a[2]), "r"(a[3]), "r"(b[0]), "r"(b[1]));
}

// D[8] = x@Wx + s@Wh (3 split terms each, 2 n-tiles)
__device__ __forceinline__ void gate_mma(float* d,
        const u32* xh, const u32* xl, const u32* sh, const u32* sl,
        const u32 Bx[2][2][2], const u32 Bh[2][2][2]) {
#pragma unroll
    for (int nt = 0; nt < 2; nt++) {
        float* dd = d + nt * 4;
        dd[0] = dd[1] = dd[2] = dd[3] = 0.0f;
        mma16816(dd, xh, Bx[nt][0]);  // hi*hi
        mma16816(dd, xh, Bx[nt][1]);  // hi*lo
        mma16816(dd, xl, Bx[nt][0]);  // lo*hi
        mma16816(dd, sh, Bh[nt][0]);
        mma16816(dd, sh, Bh[nt][1]);
        mma16816(dd, sl, Bh[nt][0]);
    }
}

__global__ void __launch_bounds__(NTHR, 3) augru_kernel(
    const float* __restrict__ X, const float* __restrict__ A,
    const float* __restrict__ H0, float* __restrict__ Out)
{
    __shared__ __align__(16) float xsf[TC][ROWS_PER_CTA][XP];
    __shared__ __align__(16) float asf[TC][ROWS_PER_CTA][XP];

    const int tid  = threadIdx.x;
    const int lane = tid & 31;
    const int wrow = (tid >> 5) * 16;       // warp's local row base (0,16,32,48)
    const int g    = lane >> 2;
    const int tig  = lane & 3;
    const int rowBase = blockIdx.x * ROWS_PER_CTA;

    // load B fragments into registers (once)
    u32 Bf[6][2][2][2];
#pragma unroll
    for (int m = 0; m < 6; m++)
#pragma unroll
        for (int nt = 0; nt < 2; nt++)
#pragma unroll
            for (int term = 0; term < 2; term++)
#pragma unroll
                for (int reg = 0; reg < 2; reg++)
                    Bf[m][nt][term][reg] =
                        gB[(((m * 2 + nt) * 2 + term) * 2 + reg) * 32 + lane];

    // init padding cols 10..17 (x col10 = 1.0 bias; rest 0). Written once.
    {
        int tc = tid >> 6, row = tid & 63;
        xsf[tc][row][10] = 1.0f;
#pragma unroll
        for (int c = 11; c < XP; c++) xsf[tc][row][c] = 0.0f;
#pragma unroll
        for (int c = 10; c < XP; c++) asf[tc][row][c] = 0.0f;
    }

    // h in D-layout: [0,1]=(g,2t..),[2,3]=(g+8,2t..),[4..7]=cols+8
    float h[8];
    {
        float c0 = H0[2 * tig], c1 = H0[2 * tig + 1];
        h[0] = c0; h[1] = c1; h[2] = c0; h[3] = c1;
        float c4 = (8 + 2 * tig < E_) ? H0[8 + 2 * tig] : 0.0f;
        float c5 = (9 + 2 * tig < E_) ? H0[9 + 2 * tig] : 0.0f;
        h[4] = c4; h[5] = c5; h[6] = c4; h[7] = c5;
    }

    const float4* Xg = reinterpret_cast<const float4*>(X);
    const float4* Ag = reinterpret_cast<const float4*>(A);

#pragma unroll 1
    for (int t0 = 0; t0 < T_; t0 += TC) {
        __syncthreads();
        // stage 2 steps of x,a for 64 rows (coalesced float4; 5 f4/row)
        {
            const long cbase = (long)(t0 * E_) / 4;
#pragma unroll
            for (int it = 0; it < 3; ++it) {
                int idx = it * NTHR + tid;                 // 0..383, use <320
                if (idx < 320) {
                    int r = idx / 5, v = idx % 5;
                    long gg = (long)(rowBase + r) * 125 + cbase + v;
                    float4 dx = Xg[gg];
                    float4 da = Ag[gg];
#pragma unroll
                    for (int c = 0; c < 4; c++) {
                        int q = v * 4 + c;
                        int tl = (q >= E_) ? 1 : 0;
                        int e = q - E_ * tl;
                        float fx = (c == 0) ? dx.x : (c == 1) ? dx.y : (c == 2) ? dx.z : dx.w;
                        float fa = (c == 0) ? da.x : (c == 1) ? da.y : (c == 2) ? da.z : da.w;
                        xsf[tl][r][e] = fx;
                        asf[tl][r][e] = fa;
                    }
                }
            }
        }
        __syncthreads();

#pragma unroll 1
        for (int tt = 0; tt < TC; ++tt) {
            // x A-fragments (hi/lo)
            u32 xh[4], xl[4];
            {
                float2 p;
                p = *reinterpret_cast<const float2*>(&xsf[tt][wrow + g][2 * tig]);
                split2(p.x, p.y, xh[0], xl[0]);
                p = *reinterpret_cast<const float2*>(&xsf[tt][wrow + g + 8][2 * tig]);
                split2(p.x, p.y, xh[1], xl[1]);
                p = *reinterpret_cast<const float2*>(&xsf[tt][wrow + g][2 * tig + 8]);
                split2(p.x, p.y, xh[2], xl[2]);
                p = *reinterpret_cast<const float2*>(&xsf[tt][wrow + g + 8][2 * tig + 8]);
                split2(p.x, p.y, xh[3], xl[3]);
            }
            // h A-fragments (D->A is in-lane)
            u32 hh[4], hl[4];
            split2(h[0], h[1], hh[0], hl[0]);
            split2(h[2], h[3], hh[1], hl[1]);
            split2(h[4], h[5], hh[2], hl[2]);
            split2(h[6], h[7], hh[3], hl[3]);

            // z gate -> hz
            float d[8];
            gate_mma(d, xh, xl, hh, hl, Bf[2], Bf[3]);
            float hzv[8];
#pragma unroll
            for (int i = 0; i < 8; i++) hzv[i] = h[i] * sigm(d[i]);
            u32 zh[4], zl[4];
            split2(hzv[0], hzv[1], zh[0], zl[0]);
            split2(hzv[2], hzv[3], zh[1], zl[1]);
            split2(hzv[4], hzv[5], zh[2], zl[2]);
            split2(hzv[6], hzv[7], zh[3], zl[3]);

            // r gate
            float rd[8];
            gate_mma(rd, xh, xl, hh, hl, Bf[0], Bf[1]);
#pragma unroll
            for (int i = 0; i < 8; i++) rd[i] = sigm(rd[i]);

            // candidate
            gate_mma(d, xh, xl, zh, zl, Bf[4], Bf[5]);

            // h update (a_t in D-layout from shared)
            float av[8];
            {
                float2 p;
                p = *reinterpret_cast<const float2*>(&asf[tt][wrow + g][2 * tig]);
                av[0] = p.x; av[1] = p.y;
                p = *reinterpret_cast<const float2*>(&asf[tt][wrow + g + 8][2 * tig]);
                av[2] = p.x; av[3] = p.y;
                p = *reinterpret_cast<const float2*>(&asf[tt][wrow + g][2 * tig + 8]);
                av[4] = p.x; av[5] = p.y;
                p = *reinterpret_cast<const float2*>(&asf[tt][wrow + g + 8][2 * tig + 8]);
                av[6] = p.x; av[7] = p.y;
            }
#pragma unroll
            for (int i = 0; i < 8; i++) {
                float c  = tanh_f(d[i]);
                float Ra = av[i] * rd[i];
                h[i] += Ra * (c - h[i]);
            }
        }
    }

    // store final h (cols >= 10 are padded; skip)
    {
        long row0 = rowBase + wrow + g;
        long row1 = row0 + 8;
        *reinterpret_cast<float2*>(&Out[row0 * E_ + 2 * tig]) = make_float2(h[0], h[1]);
        *reinterpret_cast<float2*>(&Out[row1 * E_ + 2 * tig]) = make_float2(h[2], h[3]);
        if (tig == 0) {
            *reinterpret_cast<float2*>(&Out[row0 * E_ + 8]) = make_float2(h[4], h[5]);
            *reinterpret_cast<float2*>(&Out[row1 * E_ + 8]) = make_float2(h[6], h[7]);
        }
    }
}

extern "C" void kernel_launch(void* const* d_in, const int* in_sizes, int n_in,
                              void* d_out, int out_size) {
    const float* X   = (const float*)d_in[0];
    const float* A   = (const float*)d_in[1];
    const float* H0  = (const float*)d_in[2];
    const float* WiR = (const float*)d_in[3];
    const float* biR = (const float*)d_in[4];
    const float* WhR = (const float*)d_in[5];
    const float* WsR = (const float*)d_in[6];
    const float* bsR = (const float*)d_in[7];
    const float* WiZ = (const float*)d_in[8];
    const float* biZ = (const float*)d_in[9];
    const float* WhZ = (const float*)d_in[10];
    const float* WsZ = (const float*)d_in[11];
    const float* bsZ = (const float*)d_in[12];
    const float* WiH = (const float*)d_in[13];
    const float* biH = (const float*)d_in[14];
    const float* WhH = (const float*)d_in[15];
    const float* WtH = (const float*)d_in[16];
    const float* btH = (const float*)d_in[17];
    float* Out = (float*)d_out;

    prep_kernel<<<1, 256>>>(WiR, biR, WhR, WsR, bsR,
                            WiZ, biZ, WhZ, WsZ, bsZ,
                            WiH, biH, WhH, WtH, btH);

    dim3 grid(BTOT / ROWS_PER_CTA);  // 1024
    dim3 block(NTHR);                // 128
    augru_kernel<<<grid, block>>>(X, A, H0, Out);
}

// round 16
// speedup vs baseline: 2.1648x; 1.0676x over previous
#include <cuda_runtime.h>
#include <cuda_bf16.h>

// AUGRU: B=65536, T=50, E=10 — tensor-core path (mma.sync.m16n8k16 bf16,
// two-term hi/lo split). r14 analysis: MUFU was the hidden top pipe (58% busy:
// 24 act/thread-step x 2 MUFU (EX2+RCP) x rt8). This round: r/z sigmoids via
// hardware MUFU.TANH  (sigm(v)=0.5*tanh(0.5v)+0.5, 1 MUFU) -> 48->32 MUFU per
// warp-step. Candidate tanh stays exp-based (accurate): its error enters h
// directly, sigmoid errors are attenuated by the gate structure.

#define E_   10
#define T_   50
#define BTOT 65536
#define ROWS_PER_CTA 64
#define NTHR 128
#define TC   2
#define XP   18           // staging row pitch (floats)

typedef unsigned int u32;

// B-fragments: [(((m*2+nt)*2+term)*2+reg)*32 + lane]
// m: 0=Wx_r,1=Wh_r,2=Wx_z,3=Wh_z,4=Wx_c,5=Wh_c (x-side holds bias row 10)
__device__ u32 gB[1536];

// pack: low16 = bf16(lo), high16 = bf16(hi)  (PTX: first src -> high half)
__device__ __forceinline__ u32 packbf(float lo, float hi) {
    u32 r; asm("cvt.rn.bf16x2.f32 %0, %1, %2;" : "=r"(r) : "f"(hi), "f"(lo));
    return r;
}
// split (v0,v1) into hi bf16x2 and residual-lo bf16x2
__device__ __forceinline__ void split2(float v0, float v1, u32& hi_, u32& lo_) {
    u32 h = packbf(v0, v1);
    float h0 = __uint_as_float(h << 16);
    float h1 = __uint_as_float(h & 0xffff0000u);
    hi_ = h;
    lo_ = packbf(v0 - h0, v1 - h1);
}

__global__ void prep_kernel(
    const float* __restrict__ WiR, const float* __restrict__ biR, const float* __restrict__ WhR,
    const float* __restrict__ WsR, const float* __restrict__ bsR,
    const float* __restrict__ WiZ, const float* __restrict__ biZ, const float* __restrict__ WhZ,
    const float* __restrict__ WsZ, const float* __restrict__ bsZ,
    const float* __restrict__ WiH, const float* __restrict__ biH, const float* __restrict__ WhH,
    const float* __restrict__ WtH, const float* __restrict__ btH)
{
    __shared__ float Wf[6][16][16];   // [m][k][n], zero-padded
    const int t = threadIdx.x;        // 256 threads
    for (int i = t; i < 6 * 256; i += 256)
        (&Wf[0][0][0])[i] = 0.0f;
    __syncthreads();

    const float* Am[6] = {WiR, WhR, WiZ, WhZ, WiH, WhH};
    const float* Bm[6] = {WsR, WsR, WsZ, WsZ, WtH, WtH};
    if (t < 100) {
        int k = t / E_, j = t % E_;
#pragma unroll
        for (int m = 0; m < 6; m++) {
            float s = 0.0f;
#pragma unroll
            for (int l = 0; l < E_; l++)
                s = fmaf(Am[m][k * E_ + l], Bm[m][l * E_ + j], s);
            Wf[m][k][j] = s;
        }
    }
    const float* bi[3] = {biR, biZ, biH};
    const float* bs[3] = {bsR, bsZ, btH};
    const float* Wo[3] = {WsR, WsZ, WtH};
    if (t < E_) {
#pragma unroll
        for (int m = 0; m < 3; m++) {
            float s = bs[m][t];
#pragma unroll
            for (int l = 0; l < E_; l++)
                s = fmaf(bi[m][l], Wo[m][l * E_ + t], s);
            Wf[2 * m][10][t] = s;     // bias -> x-side row 10 (m=0,2,4)
        }
    }
    __syncthreads();

    // pack B fragments (m16n8k16 col-major B: b0 k-rows {2t,2t+1}, b1 +8; col=g)
    for (int i = t; i < 1536; i += 256) {
        int lane = i & 31; int j = i >> 5;
        int reg = j & 1; j >>= 1;
        int term = j & 1; j >>= 1;
        int nt = j & 1; int m = j >> 1;
        int g = lane >> 2, tig = lane & 3;
        int k0 = 2 * tig + (reg ? 8 : 0);
        int col = nt * 8 + g;
        u32 hi, lo;
        split2(Wf[m][k0][col], Wf[m][k0 + 1][col], hi, lo);
        gB[i] = term ? lo : hi;
    }
}

// fast sigmoid: 0.5*tanh(0.5v)+0.5 — one MUFU.TANH (max abs err ~5e-4 on tanh
// -> ~2.5e-4 on sigmoid; attenuated by gate structure before reaching h).
__device__ __forceinline__ float sigm_fast(float v) {
    float t;
    asm("tanh.approx.f32 %0, %1;" : "=f"(t) : "f"(0.5f * v));
    return fmaf(0.5f, t, 0.5f);
}
// accurate tanh for the candidate (errors here hit h directly)
__device__ __forceinline__ float tanh_f(float v) {
    float e = __expf(2.0f * v);
    return 1.0f - __fdividef(2.0f, 1.0f + e);
}

__device__ __forceinline__ void mma16816(float* d, const u32* a, const u32* b) {
    asm("mma.sync.aligned.m16n8k16.row.col.f32.bf16.bf16.f32 "
        "{%0,%1,%2,%3},{%4,%5,%6,%7},{%8,%9},{%0,%1,%2,%3};"
        : "+f"(d[0]), "+f"(d[1]), "+f"(d[2]), "+f"(d[3])
        : "r"(a[0]), "r"(a[1]), "r"(a[2]), "r"(a[3]), "r"(b[0]), "r"(b[1]));
}

// D[8] = x@Wx + s@Wh (3 split terms each, 2 n-tiles)
__device__ __forceinline__ void gate_mma(float* d,
        const u32* xh, const u32* xl, const u32* sh, const u32* sl,
        const u32 Bx[2][2][2], const u32 Bh[2][2][2]) {
#pragma unroll
    for (int nt = 0; nt < 2; nt++) {
        float* dd = d + nt * 4;
        dd[0] = dd[1] = dd[2] = dd[3] = 0.0f;
        mma16816(dd, xh, Bx[nt][0]);  // hi*hi
        mma16816(dd, xh, Bx[nt][1]);  // hi*lo
        mma16816(dd, xl, Bx[nt][0]);  // lo*hi
        mma16816(dd, sh, Bh[nt][0]);
        mma16816(dd, sh, Bh[nt][1]);
        mma16816(dd, sl, Bh[nt][0]);
    }
}

__global__ void __launch_bounds__(NTHR, 3) augru_kernel(
    const float* __restrict__ X, const float* __restrict__ A,
    const float* __restrict__ H0, float* __restrict__ Out)
{
    __shared__ __align__(16) float xsf[TC][ROWS_PER_CTA][XP];
    __shared__ __align__(16) float asf[TC][ROWS_PER_CTA][XP];

    const int tid  = threadIdx.x;
    const int lane = tid & 31;
    const int wrow = (tid >> 5) * 16;       // warp's local row base (0,16,32,48)
    const int g    = lane >> 2;
    const int tig  = lane & 3;
    const int rowBase = blockIdx.x * ROWS_PER_CTA;

    // load B fragments into registers (once)
    u32 Bf[6][2][2][2];
#pragma unroll
    for (int m = 0; m < 6; m++)
#pragma unroll
        for (int nt = 0; nt < 2; nt++)
#pragma unroll
            for (int term = 0; term < 2; term++)
#pragma unroll
                for (int reg = 0; reg < 2; reg++)
                    Bf[m][nt][term][reg] =
                        gB[(((m * 2 + nt) * 2 + term) * 2 + reg) * 32 + lane];

    // init padding cols 10..17 (x col10 = 1.0 bias; rest 0). Written once.
    {
        int tc = tid >> 6, row = tid & 63;
        xsf[tc][row][10] = 1.0f;
#pragma unroll
        for (int c = 11; c < XP; c++) xsf[tc][row][c] = 0.0f;
#pragma unroll
        for (int c = 10; c < XP; c++) asf[tc][row][c] = 0.0f;
    }

    // h in D-layout: [0,1]=(g,2t..),[2,3]=(g+8,2t..),[4..7]=cols+8
    float h[8];
    {
        float c0 = H0[2 * tig], c1 = H0[2 * tig + 1];
        h[0] = c0; h[1] = c1; h[2] = c0; h[3] = c1;
        float c4 = (8 + 2 * tig < E_) ? H0[8 + 2 * tig] : 0.0f;
        float c5 = (9 + 2 * tig < E_) ? H0[9 + 2 * tig] : 0.0f;
        h[4] = c4; h[5] = c5; h[6] = c4; h[7] = c5;
    }

    const float4* Xg = reinterpret_cast<const float4*>(X);
    const float4* Ag = reinterpret_cast<const float4*>(A);

#pragma unroll 1
    for (int t0 = 0; t0 < T_; t0 += TC) {
        __syncthreads();
        // stage 2 steps of x,a for 64 rows (coalesced float4; 5 f4/row)
        {
            const long cbase = (long)(t0 * E_) / 4;
#pragma unroll
            for (int it = 0; it < 3; ++it) {
                int idx = it * NTHR + tid;                 // 0..383, use <320
                if (idx < 320) {
                    int r = idx / 5, v = idx % 5;
                    long gg = (long)(rowBase + r) * 125 + cbase + v;
                    float4 dx = Xg[gg];
                    float4 da = Ag[gg];
#pragma unroll
                    for (int c = 0; c < 4; c++) {
                        int q = v * 4 + c;
                        int tl = (q >= E_) ? 1 : 0;
                        int e = q - E_ * tl;
                        float fx = (c == 0) ? dx.x : (c == 1) ? dx.y : (c == 2) ? dx.z : dx.w;
                        float fa = (c == 0) ? da.x : (c == 1) ? da.y : (c == 2) ? da.z : da.w;
                        xsf[tl][r][e] = fx;
                        asf[tl][r][e] = fa;
                    }
                }
            }
        }
        __syncthreads();

#pragma unroll 1
        for (int tt = 0; tt < TC; ++tt) {
            // x A-fragments (hi/lo)
            u32 xh[4], xl[4];
            {
                float2 p;
                p = *reinterpret_cast<const float2*>(&xsf[tt][wrow + g][2 * tig]);
                split2(p.x, p.y, xh[0], xl[0]);
                p = *reinterpret_cast<const float2*>(&xsf[tt][wrow + g + 8][2 * tig]);
                split2(p.x, p.y, xh[1], xl[1]);
                p = *reinterpret_cast<const float2*>(&xsf[tt][wrow + g][2 * tig + 8]);
                split2(p.x, p.y, xh[2], xl[2]);
                p = *reinterpret_cast<const float2*>(&xsf[tt][wrow + g + 8][2 * tig + 8]);
                split2(p.x, p.y, xh[3], xl[3]);
            }
            // h A-fragments (D->A is in-lane)
            u32 hh[4], hl[4];
            split2(h[0], h[1], hh[0], hl[0]);
            split2(h[2], h[3], hh[1], hl[1]);
            split2(h[4], h[5], hh[2], hl[2]);
            split2(h[6], h[7], hh[3], hl[3]);

            // z gate -> hz   (sigmoid via MUFU.TANH)
            float d[8];
            gate_mma(d, xh, xl, hh, hl, Bf[2], Bf[3]);
            float hzv[8];
#pragma unroll
            for (int i = 0; i < 8; i++) hzv[i] = h[i] * sigm_fast(d[i]);
            u32 zh[4], zl[4];
            split2(hzv[0], hzv[1], zh[0], zl[0]);
            split2(hzv[2], hzv[3], zh[1], zl[1]);
            split2(hzv[4], hzv[5], zh[2], zl[2]);
            split2(hzv[6], hzv[7], zh[3], zl[3]);

            // r gate   (sigmoid via MUFU.TANH)
            float rd[8];
            gate_mma(rd, xh, xl, hh, hl, Bf[0], Bf[1]);
#pragma unroll
            for (int i = 0; i < 8; i++) rd[i] = sigm_fast(rd[i]);

            // candidate (accurate tanh)
            gate_mma(d, xh, xl, zh, zl, Bf[4], Bf[5]);

            // h update (a_t in D-layout from shared)
            float av[8];
            {
                float2 p;
                p = *reinterpret_cast<const float2*>(&asf[tt][wrow + g][2 * tig]);
                av[0] = p.x; av[1] = p.y;
                p = *reinterpret_cast<const float2*>(&asf[tt][wrow + g + 8][2 * tig]);
                av[2] = p.x; av[3] = p.y;
                p = *reinterpret_cast<const float2*>(&asf[tt][wrow + g][2 * tig + 8]);
                av[4] = p.x; av[5] = p.y;
                p = *reinterpret_cast<const float2*>(&asf[tt][wrow + g + 8][2 * tig + 8]);
                av[6] = p.x; av[7] = p.y;
            }
#pragma unroll
            for (int i = 0; i < 8; i++) {
                float c  = tanh_f(d[i]);
                float Ra = av[i] * rd[i];
                h[i] += Ra * (c - h[i]);
            }
        }
    }

    // store final h (cols >= 10 are padded; skip)
    {
        long row0 = rowBase + wrow + g;
        long row1 = row0 + 8;
        *reinterpret_cast<float2*>(&Out[row0 * E_ + 2 * tig]) = make_float2(h[0], h[1]);
        *reinterpret_cast<float2*>(&Out[row1 * E_ + 2 * tig]) = make_float2(h[2], h[3]);
        if (tig == 0) {
            *reinterpret_cast<float2*>(&Out[row0 * E_ + 8]) = make_float2(h[4], h[5]);
            *reinterpret_cast<float2*>(&Out[row1 * E_ + 8]) = make_float2(h[6], h[7]);
        }
    }
}

extern "C" void kernel_launch(void* const* d_in, const int* in_sizes, int n_in,
                              void* d_out, int out_size) {
    const float* X   = (const float*)d_in[0];
    const float* A   = (const float*)d_in[1];
    const float* H0  = (const float*)d_in[2];
    const float* WiR = (const float*)d_in[3];
    const float* biR = (const float*)d_in[4];
    const float* WhR = (const float*)d_in[5];
    const float* WsR = (const float*)d_in[6];
    const float* bsR = (const float*)d_in[7];
    const float* WiZ = (const float*)d_in[8];
    const float* biZ = (const float*)d_in[9];
    const float* WhZ = (const float*)d_in[10];
    const float* WsZ = (const float*)d_in[11];
    const float* bsZ = (const float*)d_in[12];
    const float* WiH = (const float*)d_in[13];
    const float* biH = (const float*)d_in[14];
    const float* WhH = (const float*)d_in[15];
    const float* WtH = (const float*)d_in[16];
    const float* btH = (const float*)d_in[17];
    float* Out = (float*)d_out;

    prep_kernel<<<1, 256>>>(WiR, biR, WhR, WsR, bsR,
                            WiZ, biZ, WhZ, WsZ, bsZ,
                            WiH, biH, WhH, WtH, btH);

    dim3 grid(BTOT / ROWS_PER_CTA);  // 1024
    dim3 block(NTHR);                // 128
    augru_kernel<<<grid, block>>>(X, A, H0, Out);
}

// round 17
// speedup vs baseline: 2.2493x; 1.0390x over previous
#include <cuda_runtime.h>
#include <cuda_bf16.h>

// AUGRU: B=65536, T=50, E=10 — tensor-core path (mma.sync.m16n8k16 bf16,
// two-term hi/lo split). MUFU is the binder (r16: 32 warp-MUFU x rt8 = 256 of
// 315 cyc/warp-step). r16 measured that activation approx error is attenuated
// ~100x by the gate structure (sigmoids exp->MUFU.TANH moved rel_err by only
// 4e-7). This round: candidate tanh -> hardware tanh.approx.f32 (1 MUFU, no
// glue): MUFU 32->24/warp-step, bound 256->192 cyc.

#define E_   10
#define T_   50
#define BTOT 65536
#define ROWS_PER_CTA 64
#define NTHR 128
#define TC   2
#define XP   18           // staging row pitch (floats)

typedef unsigned int u32;

// B-fragments: [(((m*2+nt)*2+term)*2+reg)*32 + lane]
// m: 0=Wx_r,1=Wh_r,2=Wx_z,3=Wh_z,4=Wx_c,5=Wh_c (x-side holds bias row 10)
__device__ u32 gB[1536];

// pack: low16 = bf16(lo), high16 = bf16(hi)  (PTX: first src -> high half)
__device__ __forceinline__ u32 packbf(float lo, float hi) {
    u32 r; asm("cvt.rn.bf16x2.f32 %0, %1, %2;" : "=r"(r) : "f"(hi), "f"(lo));
    return r;
}
// split (v0,v1) into hi bf16x2 and residual-lo bf16x2
__device__ __forceinline__ void split2(float v0, float v1, u32& hi_, u32& lo_) {
    u32 h = packbf(v0, v1);
    float h0 = __uint_as_float(h << 16);
    float h1 = __uint_as_float(h & 0xffff0000u);
    hi_ = h;
    lo_ = packbf(v0 - h0, v1 - h1);
}

__global__ void prep_kernel(
    const float* __restrict__ WiR, const float* __restrict__ biR, const float* __restrict__ WhR,
    const float* __restrict__ WsR, const float* __restrict__ bsR,
    const float* __restrict__ WiZ, const float* __restrict__ biZ, const float* __restrict__ WhZ,
    const float* __restrict__ WsZ, const float* __restrict__ bsZ,
    const float* __restrict__ WiH, const float* __restrict__ biH, const float* __restrict__ WhH,
    const float* __restrict__ WtH, const float* __restrict__ btH)
{
    __shared__ float Wf[6][16][16];   // [m][k][n], zero-padded
    const int t = threadIdx.x;        // 256 threads
    for (int i = t; i < 6 * 256; i += 256)
        (&Wf[0][0][0])[i] = 0.0f;
    __syncthreads();

    const float* Am[6] = {WiR, WhR, WiZ, WhZ, WiH, WhH};
    const float* Bm[6] = {WsR, WsR, WsZ, WsZ, WtH, WtH};
    if (t < 100) {
        int k = t / E_, j = t % E_;
#pragma unroll
        for (int m = 0; m < 6; m++) {
            float s = 0.0f;
#pragma unroll
            for (int l = 0; l < E_; l++)
                s = fmaf(Am[m][k * E_ + l], Bm[m][l * E_ + j], s);
            Wf[m][k][j] = s;
        }
    }
    const float* bi[3] = {biR, biZ, biH};
    const float* bs[3] = {bsR, bsZ, btH};
    const float* Wo[3] = {WsR, WsZ, WtH};
    if (t < E_) {
#pragma unroll
        for (int m = 0; m < 3; m++) {
            float s = bs[m][t];
#pragma unroll
            for (int l = 0; l < E_; l++)
                s = fmaf(bi[m][l], Wo[m][l * E_ + t], s);
            Wf[2 * m][10][t] = s;     // bias -> x-side row 10 (m=0,2,4)
        }
    }
    __syncthreads();

    // pack B fragments (m16n8k16 col-major B: b0 k-rows {2t,2t+1}, b1 +8; col=g)
    for (int i = t; i < 1536; i += 256) {
        int lane = i & 31; int j = i >> 5;
        int reg = j & 1; j >>= 1;
        int term = j & 1; j >>= 1;
        int nt = j & 1; int m = j >> 1;
        int g = lane >> 2, tig = lane & 3;
        int k0 = 2 * tig + (reg ? 8 : 0);
        int col = nt * 8 + g;
        u32 hi, lo;
        split2(Wf[m][k0][col], Wf[m][k0 + 1][col], hi, lo);
        gB[i] = term ? lo : hi;
    }
}

// fast sigmoid: 0.5*tanh(0.5v)+0.5 — one MUFU.TANH (error attenuated by the
// gate structure; measured contribution ~4e-7 aggregate in r16).
__device__ __forceinline__ float sigm_fast(float v) {
    float t;
    asm("tanh.approx.f32 %0, %1;" : "=f"(t) : "f"(0.5f * v));
    return fmaf(0.5f, t, 0.5f);
}
// fast tanh for the candidate: hardware MUFU.TANH (1 MUFU, no glue).
__device__ __forceinline__ float tanh_fast(float v) {
    float t;
    asm("tanh.approx.f32 %0, %1;" : "=f"(t) : "f"(v));
    return t;
}

__device__ __forceinline__ void mma16816(float* d, const u32* a, const u32* b) {
    asm("mma.sync.aligned.m16n8k16.row.col.f32.bf16.bf16.f32 "
        "{%0,%1,%2,%3},{%4,%5,%6,%7},{%8,%9},{%0,%1,%2,%3};"
        : "+f"(d[0]), "+f"(d[1]), "+f"(d[2]), "+f"(d[3])
        : "r"(a[0]), "r"(a[1]), "r"(a[2]), "r"(a[3]), "r"(b[0]), "r"(b[1]));
}

// D[8] = x@Wx + s@Wh (3 split terms each, 2 n-tiles)
__device__ __forceinline__ void gate_mma(float* d,
        const u32* xh, const u32* xl, const u32* sh, const u32* sl,
        const u32 Bx[2][2][2], const u32 Bh[2][2][2]) {
#pragma unroll
    for (int nt = 0; nt < 2; nt++) {
        float* dd = d + nt * 4;
        dd[0] = dd[1] = dd[2] = dd[3] = 0.0f;
        mma16816(dd, xh, Bx[nt][0]);  // hi*hi
        mma16816(dd, xh, Bx[nt][1]);  // hi*lo
        mma16816(dd, xl, Bx[nt][0]);  // lo*hi
        mma16816(dd, sh, Bh[nt][0]);
        mma16816(dd, sh, Bh[nt][1]);
        mma16816(dd, sl, Bh[nt][0]);
    }
}

__global__ void __launch_bounds__(NTHR, 3) augru_kernel(
    const float* __restrict__ X, const float* __restrict__ A,
    const float* __restrict__ H0, float* __restrict__ Out)
{
    __shared__ __align__(16) float xsf[TC][ROWS_PER_CTA][XP];
    __shared__ __align__(16) float asf[TC][ROWS_PER_CTA][XP];

    const int tid  = threadIdx.x;
    const int lane = tid & 31;
    const int wrow = (tid >> 5) * 16;       // warp's local row base (0,16,32,48)
    const int g    = lane >> 2;
    const int tig  = lane & 3;
    const int rowBase = blockIdx.x * ROWS_PER_CTA;

    // load B fragments into registers (once)
    u32 Bf[6][2][2][2];
#pragma unroll
    for (int m = 0; m < 6; m++)
#pragma unroll
        for (int nt = 0; nt < 2; nt++)
#pragma unroll
            for (int term = 0; term < 2; term++)
#pragma unroll
                for (int reg = 0; reg < 2; reg++)
                    Bf[m][nt][term][reg] =
                        gB[(((m * 2 + nt) * 2 + term) * 2 + reg) * 32 + lane];

    // init padding cols 10..17 (x col10 = 1.0 bias; rest 0). Written once.
    {
        int tc = tid >> 6, row = tid & 63;
        xsf[tc][row][10] = 1.0f;
#pragma unroll
        for (int c = 11; c < XP; c++) xsf[tc][row][c] = 0.0f;
#pragma unroll
        for (int c = 10; c < XP; c++) asf[tc][row][c] = 0.0f;
    }

    // h in D-layout: [0,1]=(g,2t..),[2,3]=(g+8,2t..),[4..7]=cols+8
    float h[8];
    {
        float c0 = H0[2 * tig], c1 = H0[2 * tig + 1];
        h[0] = c0; h[1] = c1; h[2] = c0; h[3] = c1;
        float c4 = (8 + 2 * tig < E_) ? H0[8 + 2 * tig] : 0.0f;
        float c5 = (9 + 2 * tig < E_) ? H0[9 + 2 * tig] : 0.0f;
        h[4] = c4; h[5] = c5; h[6] = c4; h[7] = c5;
    }

    const float4* Xg = reinterpret_cast<const float4*>(X);
    const float4* Ag = reinterpret_cast<const float4*>(A);

#pragma unroll 1
    for (int t0 = 0; t0 < T_; t0 += TC) {
        __syncthreads();
        // stage 2 steps of x,a for 64 rows (coalesced float4; 5 f4/row)
        {
            const long cbase = (long)(t0 * E_) / 4;
#pragma unroll
            for (int it = 0; it < 3; ++it) {
                int idx = it * NTHR + tid;                 // 0..383, use <320
                if (idx < 320) {
                    int r = idx / 5, v = idx % 5;
                    long gg = (long)(rowBase + r) * 125 + cbase + v;
                    float4 dx = Xg[gg];
                    float4 da = Ag[gg];
#pragma unroll
                    for (int c = 0; c < 4; c++) {
                        int q = v * 4 + c;
                        int tl = (q >= E_) ? 1 : 0;
                        int e = q - E_ * tl;
                        float fx = (c == 0) ? dx.x : (c == 1) ? dx.y : (c == 2) ? dx.z : dx.w;
                        float fa = (c == 0) ? da.x : (c == 1) ? da.y : (c == 2) ? da.z : da.w;
                        xsf[tl][r][e] = fx;
                        asf[tl][r][e] = fa;
                    }
                }
            }
        }
        __syncthreads();

#pragma unroll 1
        for (int tt = 0; tt < TC; ++tt) {
            // x A-fragments (hi/lo)
            u32 xh[4], xl[4];
            {
                float2 p;
                p = *reinterpret_cast<const float2*>(&xsf[tt][wrow + g][2 * tig]);
                split2(p.x, p.y, xh[0], xl[0]);
                p = *reinterpret_cast<const float2*>(&xsf[tt][wrow + g + 8][2 * tig]);
                split2(p.x, p.y, xh[1], xl[1]);
                p = *reinterpret_cast<const float2*>(&xsf[tt][wrow + g][2 * tig + 8]);
                split2(p.x, p.y, xh[2], xl[2]);
                p = *reinterpret_cast<const float2*>(&xsf[tt][wrow + g + 8][2 * tig + 8]);
                split2(p.x, p.y, xh[3], xl[3]);
            }
            // h A-fragments (D->A is in-lane)
            u32 hh[4], hl[4];
            split2(h[0], h[1], hh[0], hl[0]);
            split2(h[2], h[3], hh[1], hl[1]);
            split2(h[4], h[5], hh[2], hl[2]);
            split2(h[6], h[7], hh[3], hl[3]);

            // z gate -> hz   (sigmoid via MUFU.TANH)
            float d[8];
            gate_mma(d, xh, xl, hh, hl, Bf[2], Bf[3]);
            float hzv[8];
#pragma unroll
            for (int i = 0; i < 8; i++) hzv[i] = h[i] * sigm_fast(d[i]);
            u32 zh[4], zl[4];
            split2(hzv[0], hzv[1], zh[0], zl[0]);
            split2(hzv[2], hzv[3], zh[1], zl[1]);
            split2(hzv[4], hzv[5], zh[2], zl[2]);
            split2(hzv[6], hzv[7], zh[3], zl[3]);

            // r gate   (sigmoid via MUFU.TANH)
            float rd[8];
            gate_mma(rd, xh, xl, hh, hl, Bf[0], Bf[1]);
#pragma unroll
            for (int i = 0; i < 8; i++) rd[i] = sigm_fast(rd[i]);

            // candidate (hardware tanh)
            gate_mma(d, xh, xl, zh, zl, Bf[4], Bf[5]);

            // h update (a_t in D-layout from shared)
            float av[8];
            {
                float2 p;
                p = *reinterpret_cast<const float2*>(&asf[tt][wrow + g][2 * tig]);
                av[0] = p.x; av[1] = p.y;
                p = *reinterpret_cast<const float2*>(&asf[tt][wrow + g + 8][2 * tig]);
                av[2] = p.x; av[3] = p.y;
                p = *reinterpret_cast<const float2*>(&asf[tt][wrow + g][2 * tig + 8]);
                av[4] = p.x; av[5] = p.y;
                p = *reinterpret_cast<const float2*>(&asf[tt][wrow + g + 8][2 * tig + 8]);
                av[6] = p.x; av[7] = p.y;
            }
#pragma unroll
            for (int i = 0; i < 8; i++) {
                float c  = tanh_fast(d[i]);
                float Ra = av[i] * rd[i];
                h[i] += Ra * (c - h[i]);
            }
        }
    }

    // store final h (cols >= 10 are padded; skip)
    {
        long row0 = rowBase + wrow + g;
        long row1 = row0 + 8;
        *reinterpret_cast<float2*>(&Out[row0 * E_ + 2 * tig]) = make_float2(h[0], h[1]);
        *reinterpret_cast<float2*>(&Out[row1 * E_ + 2 * tig]) = make_float2(h[2], h[3]);
        if (tig == 0) {
            *reinterpret_cast<float2*>(&Out[row0 * E_ + 8]) = make_float2(h[4], h[5]);
            *reinterpret_cast<float2*>(&Out[row1 * E_ + 8]) = make_float2(h[6], h[7]);
        }
    }
}

extern "C" void kernel_launch(void* const* d_in, const int* in_sizes, int n_in,
                              void* d_out, int out_size) {
    const float* X   = (const float*)d_in[0];
    const float* A   = (const float*)d_in[1];
    const float* H0  = (const float*)d_in[2];
    const float* WiR = (const float*)d_in[3];
    const float* biR = (const float*)d_in[4];
    const float* WhR = (const float*)d_in[5];
    const float* WsR = (const float*)d_in[6];
    const float* bsR = (const float*)d_in[7];
    const float* WiZ = (const float*)d_in[8];
    const float* biZ = (const float*)d_in[9];
    const float* WhZ = (const float*)d_in[10];
    const float* WsZ = (const float*)d_in[11];
    const float* bsZ = (const float*)d_in[12];
    const float* WiH = (const float*)d_in[13];
    const float* biH = (const float*)d_in[14];
    const float* WhH = (const float*)d_in[15];
    const float* WtH = (const float*)d_in[16];
    const float* btH = (const float*)d_in[17];
    float* Out = (float*)d_out;

    prep_kernel<<<1, 256>>>(WiR, biR, WhR, WsR, bsR,
                            WiZ, biZ, WhZ, WsZ, bsZ,
                            WiH, biH, WhH, WtH, btH);

    dim3 grid(BTOT / ROWS_PER_CTA);  // 1024
    dim3 block(NTHR);                // 128
    augru_kernel<<<grid, block>>>(X, A, H0, Out);
}